// round 5
// baseline (speedup 1.0000x reference)
#include <cuda_runtime.h>

#define NMAX 100000
#define FMAX 128

// Scratch (static device globals; no runtime allocation allowed)
__device__ float g_bufA[NMAX * FMAX];
__device__ float g_bufB[NMAX * FMAX];
__device__ float g_bufC[NMAX * FMAX];
__device__ float g_dinv[NMAX];
__device__ float g_sum[FMAX];
__device__ float g_sq[FMAX];
__device__ float g_scale[FMAX];
__device__ float g_shift[FMAX];
__device__ float g_pool[16 * FMAX];

static inline int ceil_div(int a, int b) { return (a + b - 1) / b; }

// ---------------- degree / normalization ----------------
__global__ void deg_init_kernel(float* dinv, int n) {
    int i = blockIdx.x * blockDim.x + threadIdx.x;
    if (i < n) dinv[i] = 1.0f;  // self-loop
}

__global__ void deg_acc_kernel(float* dinv, const int* __restrict__ dst, int E) {
    int e = blockIdx.x * blockDim.x + threadIdx.x;
    if (e < E) atomicAdd(&dinv[dst[e]], 1.0f);
}

__global__ void deg_fin_kernel(float* dinv, int n) {
    int i = blockIdx.x * blockDim.x + threadIdx.x;
    if (i < n) dinv[i] = rsqrtf(dinv[i]);
}

// ---------------- aggregation: agg = D^-1/2 (A+I) D^-1/2 x ----------------
// self-loop term + init: agg[i] = dinv[i]^2 * x[i]
__global__ void selfloop_kernel(const float* __restrict__ x, float* __restrict__ agg,
                                const float* __restrict__ dinv, int n, int C) {
    int gid = blockIdx.x * blockDim.x + threadIdx.x;
    if (gid >= n * C) return;
    int i = gid / C;
    float di = dinv[i];
    agg[gid] = di * di * x[gid];
}

// C == 3 specialization: one thread per edge
__global__ void scatter3_kernel(const float* __restrict__ x, float* __restrict__ agg,
                                const float* __restrict__ dinv,
                                const int* __restrict__ src,
                                const int* __restrict__ dst, int E) {
    int e = blockIdx.x * blockDim.x + threadIdx.x;
    if (e >= E) return;
    int s = src[e], d = dst[e];
    float nrm = dinv[s] * dinv[d];
    atomicAdd(&agg[d * 3 + 0], nrm * x[s * 3 + 0]);
    atomicAdd(&agg[d * 3 + 1], nrm * x[s * 3 + 1]);
    atomicAdd(&agg[d * 3 + 2], nrm * x[s * 3 + 2]);
}

// generic: one warp per edge, lanes over channels (coalesced gather + coalesced atomics)
__global__ void scatter_warp_kernel(const float* __restrict__ x, float* __restrict__ agg,
                                    const float* __restrict__ dinv,
                                    const int* __restrict__ src,
                                    const int* __restrict__ dst, int E, int C) {
    int gw = (blockIdx.x * blockDim.x + threadIdx.x) >> 5;
    int lane = threadIdx.x & 31;
    if (gw >= E) return;
    int s = src[gw], d = dst[gw];
    float nrm = dinv[s] * dinv[d];
    const float* xs = x + (long long)s * C;
    float* ad = agg + (long long)d * C;
    for (int c = lane; c < C; c += 32)
        atomicAdd(&ad[c], nrm * xs[c]);
}

// ---------------- GEMM: Y[n,M] = X[n,K] @ W[K,M] (+bias) (+relu) ----------------
// 256 threads, 64-row tile, full-M tile (M<=128), K chunked by 32.
// Thread layout: warp w owns rows w*8..w*8+7; lane l owns cols 4l..4l+3.
// X reads are warp-broadcast; W reads are LDS.128 conflict-free.
__global__ void gemm_kernel(const float* __restrict__ X, const float* __restrict__ W,
                            const float* __restrict__ bias, float* __restrict__ Y,
                            int n, int K, int M, int doRelu) {
    __shared__ float Ws[32][128];
    __shared__ float Xs[64][32];
    int tid = threadIdx.x;
    int lane = tid & 31;
    int wrp = tid >> 5;
    int row0 = blockIdx.x * 64;
    int c = lane * 4;

    float acc[8][4];
#pragma unroll
    for (int i = 0; i < 8; i++)
#pragma unroll
        for (int j = 0; j < 4; j++) acc[i][j] = 0.f;

    for (int k0 = 0; k0 < K; k0 += 32) {
        __syncthreads();
        // stage W chunk (zero-padded)
        for (int t = tid; t < 32 * 128; t += 256) {
            int kk = t >> 7;
            int cc = t & 127;
            int kg = k0 + kk;
            Ws[kk][cc] = (kg < K && cc < M) ? W[kg * M + cc] : 0.f;
        }
        // stage X chunk (zero-padded)
#pragma unroll
        for (int p = 0; p < 8; p++) {
            int r = wrp + p * 8;
            int gr = row0 + r;
            int kg = k0 + lane;
            Xs[r][lane] = (gr < n && kg < K) ? X[(long long)gr * K + kg] : 0.f;
        }
        __syncthreads();
#pragma unroll
        for (int kk = 0; kk < 32; kk++) {
            float4 w4 = *reinterpret_cast<const float4*>(&Ws[kk][c]);
#pragma unroll
            for (int i = 0; i < 8; i++) {
                float xv = Xs[wrp * 8 + i][kk];
                acc[i][0] = fmaf(xv, w4.x, acc[i][0]);
                acc[i][1] = fmaf(xv, w4.y, acc[i][1]);
                acc[i][2] = fmaf(xv, w4.z, acc[i][2]);
                acc[i][3] = fmaf(xv, w4.w, acc[i][3]);
            }
        }
    }

#pragma unroll
    for (int i = 0; i < 8; i++) {
        int gr = row0 + wrp * 8 + i;
        if (gr >= n) break;
#pragma unroll
        for (int j = 0; j < 4; j++) {
            int cc = c + j;
            if (cc < M) {
                float v = acc[i][j];
                if (bias) v += bias[cc];
                if (doRelu) v = fmaxf(v, 0.f);
                Y[(long long)gr * M + cc] = v;
            }
        }
    }
}

// ---------------- batchnorm ----------------
__global__ void zero_kernel(float* p, int nels) {
    int gid = blockIdx.x * blockDim.x + threadIdx.x;
    if (gid < nels) p[gid] = 0.f;
}

// per-block partial sums over 256 rows, thread = channel
__global__ void bn_stats_kernel(const float* __restrict__ y, int n, int C,
                                float* gsum, float* gsq) {
    int c = threadIdx.x;  // 128 threads
    if (c >= C) return;
    int r0 = blockIdx.x * 256;
    int r1 = min(r0 + 256, n);
    float s = 0.f, q = 0.f;
    for (int r = r0; r < r1; r++) {
        float v = y[(long long)r * C + c];
        s += v;
        q += v * v;
    }
    atomicAdd(&gsum[c], s);
    atomicAdd(&gsq[c], q);
}

__global__ void bn_final_kernel(const float* gsum, const float* gsq,
                                const float* __restrict__ gamma, const float* __restrict__ beta,
                                float* scale, float* shift, int n, int C) {
    int c = threadIdx.x;
    if (c >= C) return;
    float inv_n = 1.0f / (float)n;
    float m = gsum[c] * inv_n;
    float var = gsq[c] * inv_n - m * m;
    float rs = rsqrtf(var + 1e-5f);
    float sc = gamma[c] * rs;
    scale[c] = sc;
    shift[c] = beta[c] - m * sc;
}

__global__ void bn_apply_kernel(const float* __restrict__ y, float* __restrict__ xo,
                                const float* __restrict__ scale, const float* __restrict__ shift,
                                int total, int C) {
    int gid = blockIdx.x * blockDim.x + threadIdx.x;
    if (gid >= total) return;
    int c = gid % C;
    xo[gid] = fmaxf(fmaf(y[gid], scale[c], shift[c]), 0.f);
}

// ---------------- global sum pool (batch is sorted) ----------------
__global__ void pool_kernel(const float* __restrict__ x, const int* __restrict__ batch,
                            float* pooled, int n) {
    int c = threadIdx.x;  // 128
    int r0 = blockIdx.x * 512;
    int r1 = min(r0 + 512, n);
    float acc = 0.f;
    int cur = -1;
    for (int r = r0; r < r1; r++) {
        int g = batch[r];
        if (g != cur) {
            if (cur >= 0) atomicAdd(&pooled[cur * 128 + c], acc);
            acc = 0.f;
            cur = g;
        }
        acc += x[(long long)r * 128 + c];
    }
    if (cur >= 0) atomicAdd(&pooled[cur * 128 + c], acc);
}

// ---------------- MLP head on [16,128] ----------------
__global__ void head_kernel(const float* __restrict__ pooled,
                            const float* __restrict__ fw1, const float* __restrict__ fb1,
                            const float* __restrict__ fw2, const float* __restrict__ fb2,
                            const float* __restrict__ fw3, const float* __restrict__ fb3,
                            float* __restrict__ out) {
    __shared__ float s0[128], s1[128], s2[128];
    int t = threadIdx.x;
    int g = blockIdx.x;
    s0[t] = pooled[g * 128 + t];
    __syncthreads();
    float a = fb1[t];
    for (int k = 0; k < 128; k++) a = fmaf(s0[k], fw1[k * 128 + t], a);
    s1[t] = fmaxf(a, 0.f);
    __syncthreads();
    a = fb2[t];
    for (int k = 0; k < 128; k++) a = fmaf(s1[k], fw2[k * 128 + t], a);
    s2[t] = fmaxf(a, 0.f);
    __syncthreads();
    if (t < 100) {
        a = fb3[t];
        for (int k = 0; k < 128; k++) a = fmaf(s2[k], fw3[k * 100 + t], a);
        out[g * 100 + t] = a;
    }
}

// ---------------- launcher ----------------
extern "C" void kernel_launch(void* const* d_in, const int* in_sizes, int n_in,
                              void* d_out, int out_size) {
    const float* pos = (const float*)d_in[0];
    const int* ei = (const int*)d_in[1];     // int32! (JAX x64 disabled downgrades int64)
    const int* batch = (const int*)d_in[2];  // int32
    const float* w1 = (const float*)d_in[3];
    // d_in[4] = b1: cancels in BatchNorm (mean subtraction) -> skipped
    const float* g1 = (const float*)d_in[5];
    const float* be1 = (const float*)d_in[6];
    const float* w2 = (const float*)d_in[7];
    const float* g2 = (const float*)d_in[9];
    const float* be2 = (const float*)d_in[10];
    const float* w3 = (const float*)d_in[11];
    const float* g3 = (const float*)d_in[13];
    const float* be3 = (const float*)d_in[14];
    const float* fw0 = (const float*)d_in[15];
    const float* fb0 = (const float*)d_in[16];
    const float* fw1 = (const float*)d_in[17];
    const float* fb1 = (const float*)d_in[18];
    const float* fw2 = (const float*)d_in[19];
    const float* fb2 = (const float*)d_in[20];
    const float* fw3 = (const float*)d_in[21];
    const float* fb3 = (const float*)d_in[22];

    int n = in_sizes[2];       // N (batch vector length)
    int E = in_sizes[1] / 2;   // directed edges
    const int* src = ei;
    const int* dst = ei + E;

    float *A, *B, *C, *dinv, *gsum, *gsq, *scale, *shift, *pooled;
    cudaGetSymbolAddress((void**)&A, g_bufA);
    cudaGetSymbolAddress((void**)&B, g_bufB);
    cudaGetSymbolAddress((void**)&C, g_bufC);
    cudaGetSymbolAddress((void**)&dinv, g_dinv);
    cudaGetSymbolAddress((void**)&gsum, g_sum);
    cudaGetSymbolAddress((void**)&gsq, g_sq);
    cudaGetSymbolAddress((void**)&scale, g_scale);
    cudaGetSymbolAddress((void**)&shift, g_shift);
    cudaGetSymbolAddress((void**)&pooled, g_pool);

    const int T = 256;

    // degrees -> dinv
    deg_init_kernel<<<ceil_div(n, T), T>>>(dinv, n);
    deg_acc_kernel<<<ceil_div(E, T), T>>>(dinv, dst, E);
    deg_fin_kernel<<<ceil_div(n, T), T>>>(dinv, n);

    // ---- layer 1: C_in=3 -> 64 ----
    selfloop_kernel<<<ceil_div(n * 3, T), T>>>(pos, A, dinv, n, 3);
    scatter3_kernel<<<ceil_div(E, T), T>>>(pos, A, dinv, src, dst, E);
    gemm_kernel<<<ceil_div(n, 64), 256>>>(A, w1, nullptr, B, n, 3, 64, 0);
    zero_kernel<<<1, 256>>>(gsum, 128);
    zero_kernel<<<1, 256>>>(gsq, 128);
    bn_stats_kernel<<<ceil_div(n, 256), 128>>>(B, n, 64, gsum, gsq);
    bn_final_kernel<<<1, 128>>>(gsum, gsq, g1, be1, scale, shift, n, 64);
    bn_apply_kernel<<<ceil_div(n * 64, T), T>>>(B, C, scale, shift, n * 64, 64);

    // ---- layer 2: 64 -> 94 ----
    selfloop_kernel<<<ceil_div(n * 64, T), T>>>(C, A, dinv, n, 64);
    scatter_warp_kernel<<<ceil_div(E * 32, T), T>>>(C, A, dinv, src, dst, E, 64);
    gemm_kernel<<<ceil_div(n, 64), 256>>>(A, w2, nullptr, B, n, 64, 94, 0);
    zero_kernel<<<1, 256>>>(gsum, 128);
    zero_kernel<<<1, 256>>>(gsq, 128);
    bn_stats_kernel<<<ceil_div(n, 256), 128>>>(B, n, 94, gsum, gsq);
    bn_final_kernel<<<1, 128>>>(gsum, gsq, g2, be2, scale, shift, n, 94);
    bn_apply_kernel<<<ceil_div(n * 94, T), T>>>(B, C, scale, shift, n * 94, 94);

    // ---- layer 3: 94 -> 128 ----
    selfloop_kernel<<<ceil_div(n * 94, T), T>>>(C, A, dinv, n, 94);
    scatter_warp_kernel<<<ceil_div(E * 32, T), T>>>(C, A, dinv, src, dst, E, 94);
    gemm_kernel<<<ceil_div(n, 64), 256>>>(A, w3, nullptr, B, n, 94, 128, 0);
    zero_kernel<<<1, 256>>>(gsum, 128);
    zero_kernel<<<1, 256>>>(gsq, 128);
    bn_stats_kernel<<<ceil_div(n, 256), 128>>>(B, n, 128, gsum, gsq);
    bn_final_kernel<<<1, 128>>>(gsum, gsq, g3, be3, scale, shift, n, 128);
    bn_apply_kernel<<<ceil_div(n * 128, T), T>>>(B, C, scale, shift, n * 128, 128);

    // ---- fw0 + relu ----
    gemm_kernel<<<ceil_div(n, 64), 256>>>(C, fw0, fb0, B, n, 128, 128, 1);

    // ---- pool ----
    zero_kernel<<<ceil_div(16 * 128, T), T>>>(pooled, 16 * 128);
    pool_kernel<<<ceil_div(n, 512), 128>>>(B, batch, pooled, n);

    // ---- head ----
    head_kernel<<<16, 128>>>(pooled, fw1, fb1, fw2, fb2, fw3, fb3, (float*)d_out);
}

// round 6
// speedup vs baseline: 1.3526x; 1.3526x over previous
#include <cuda_runtime.h>

#define NMAX 100000
#define EMAX 600000
#define FMAX 128

// Scratch (static device globals; no runtime allocation allowed)
__device__ float g_bufA[NMAX * FMAX];
__device__ float g_bufB[NMAX * FMAX];
__device__ float g_bufC[NMAX * FMAX];
__device__ float g_dinv[NMAX];
__device__ float g_sum[FMAX];
__device__ float g_sq[FMAX];
__device__ float g_scale[FMAX];
__device__ float g_shift[FMAX];
__device__ float g_pool[16 * FMAX];
__device__ int g_cnt[NMAX];
__device__ int g_rowptr[NMAX + 1];
__device__ int g_cursor[NMAX];
__device__ int g_srcs[EMAX];
__device__ int g_bsum[1024];

static inline int ceil_div(int a, int b) { return (a + b - 1) / b; }

// ---------------- CSR build: counting sort of edges by dst ----------------
__global__ void zero_int_kernel(int* p, int n) {
    int i = blockIdx.x * blockDim.x + threadIdx.x;
    if (i < n) p[i] = 0;
}

__global__ void zero_f_kernel(float* p, int n) {
    int i = blockIdx.x * blockDim.x + threadIdx.x;
    if (i < n) p[i] = 0.f;
}

__global__ void hist_kernel(int* cnt, const int* __restrict__ dst, int E) {
    int e = blockIdx.x * blockDim.x + threadIdx.x;
    if (e < E) atomicAdd(&cnt[dst[e]], 1);
}

__global__ void scan1_kernel(const int* __restrict__ cnt, int* rowptr, int* bsum, int n) {
    __shared__ int sm[256];
    int tid = threadIdx.x;
    int gid = blockIdx.x * 256 + tid;
    int v = (gid < n) ? cnt[gid] : 0;
    sm[tid] = v;
    __syncthreads();
#pragma unroll
    for (int off = 1; off < 256; off <<= 1) {
        int t = (tid >= off) ? sm[tid - off] : 0;
        __syncthreads();
        sm[tid] += t;
        __syncthreads();
    }
    if (gid < n) rowptr[gid] = sm[tid] - v;  // exclusive
    if (tid == 255) bsum[blockIdx.x] = sm[255];
}

__global__ void scan2_kernel(int* bsum, int nb) {
    if (threadIdx.x == 0 && blockIdx.x == 0) {
        int run = 0;
        for (int b = 0; b < nb; b++) {
            int t = bsum[b];
            bsum[b] = run;
            run += t;
        }
    }
}

__global__ void scan3_kernel(int* rowptr, const int* __restrict__ bsum, int* cursor,
                             int n, int E) {
    int gid = blockIdx.x * blockDim.x + threadIdx.x;
    if (gid < n) {
        int r = rowptr[gid] + bsum[gid >> 8];
        rowptr[gid] = r;
        cursor[gid] = r;
    }
    if (gid == 0) rowptr[n] = E;
}

__global__ void reorder_kernel(const int* __restrict__ src, const int* __restrict__ dst,
                               int* cursor, int* srcs, int E) {
    int e = blockIdx.x * blockDim.x + threadIdx.x;
    if (e < E) {
        int p = atomicAdd(&cursor[dst[e]], 1);
        srcs[p] = src[e];
    }
}

__global__ void dinv_kernel(const int* __restrict__ cnt, float* dinv, int n) {
    int i = blockIdx.x * blockDim.x + threadIdx.x;
    if (i < n) dinv[i] = rsqrtf((float)(cnt[i] + 1));  // +1 self-loop
}

// ---------------- layer 1: pull-aggregate (C=3) fused with X@W1 (3->64) ----------------
__global__ void pull3_k3_kernel(const float* __restrict__ pos, const float* __restrict__ w1,
                                const float* __restrict__ dinv,
                                const int* __restrict__ rowptr, const int* __restrict__ srcs,
                                float* __restrict__ y, int n) {
    __shared__ float w1s[192];  // [3][64]
    int tid = threadIdx.x;
    if (tid < 192) w1s[tid] = w1[tid];
    __syncthreads();
    int v = blockIdx.x * blockDim.x + tid;
    if (v >= n) return;
    float di = dinv[v];
    float dd = di * di;
    float a0 = dd * pos[v * 3 + 0];
    float a1 = dd * pos[v * 3 + 1];
    float a2 = dd * pos[v * 3 + 2];
    int e1 = rowptr[v + 1];
    for (int e = rowptr[v]; e < e1; e++) {
        int s = srcs[e];
        float nrm = di * dinv[s];
        a0 = fmaf(nrm, pos[s * 3 + 0], a0);
        a1 = fmaf(nrm, pos[s * 3 + 1], a1);
        a2 = fmaf(nrm, pos[s * 3 + 2], a2);
    }
    float4* y4 = (float4*)(y + v * 64);
#pragma unroll
    for (int c4 = 0; c4 < 16; c4++) {
        float4 o;
        int c = c4 * 4;
        o.x = a0 * w1s[c + 0] + a1 * w1s[64 + c + 0] + a2 * w1s[128 + c + 0];
        o.y = a0 * w1s[c + 1] + a1 * w1s[64 + c + 1] + a2 * w1s[128 + c + 1];
        o.z = a0 * w1s[c + 2] + a1 * w1s[64 + c + 2] + a2 * w1s[128 + c + 2];
        o.w = a0 * w1s[c + 3] + a1 * w1s[64 + c + 3] + a2 * w1s[128 + c + 3];
        y4[c4] = o;
    }
}

// ---------------- generic pull-aggregate: agg = D^-1/2 (A+I) D^-1/2 x ----------------
// G = 1<<gShift lanes per node; lane handles one float4 column slot (C4 <= G).
__global__ void pull_kernel(const float* __restrict__ x, float* __restrict__ agg,
                            const float* __restrict__ dinv,
                            const int* __restrict__ rowptr, const int* __restrict__ srcs,
                            int n, int C4, int ld4, int gShift) {
    int G = 1 << gShift;
    int group = (blockIdx.x * blockDim.x + threadIdx.x) >> gShift;
    int lane = threadIdx.x & (G - 1);
    if (group >= n || lane >= C4) return;
    float di = dinv[group];
    const float4* x4 = (const float4*)x;
    float4 xv = x4[group * ld4 + lane];
    float dd = di * di;
    float4 acc = make_float4(dd * xv.x, dd * xv.y, dd * xv.z, dd * xv.w);
    int e1 = rowptr[group + 1];
    for (int e = rowptr[group]; e < e1; e++) {
        int s = srcs[e];
        float nrm = di * dinv[s];
        float4 xs = x4[s * ld4 + lane];
        acc.x = fmaf(nrm, xs.x, acc.x);
        acc.y = fmaf(nrm, xs.y, acc.y);
        acc.z = fmaf(nrm, xs.z, acc.z);
        acc.w = fmaf(nrm, xs.w, acc.w);
    }
    ((float4*)agg)[group * ld4 + lane] = acc;
}

// ---------------- GEMM: Y[n,M](ldY) = X[n,K](ldX) @ W[K,M] (+bias)(+relu)(+BN stats) ----
// 256 threads, 64-row x 128-col tile. Warp w -> rows w*8..w*8+7; lane -> cols lane*4..+3.
// Inner loop in kk-groups of 4 with float4 X broadcasts and float4 W loads.
__global__ void gemm_kernel(const float* __restrict__ X, const float* __restrict__ W,
                            const float* __restrict__ bias, float* __restrict__ Y,
                            int n, int K, int M, int ldX, int ldY, int doRelu,
                            float* gsum, float* gsq) {
    __shared__ float Ws[32][128];
    __shared__ float Xs[64][32];
    __shared__ float sSum[128], sSq[128];
    int tid = threadIdx.x;
    int lane = tid & 31;
    int wrp = tid >> 5;
    int row0 = blockIdx.x * 64;
    int c = lane * 4;

    float acc[8][4];
#pragma unroll
    for (int i = 0; i < 8; i++)
#pragma unroll
        for (int j = 0; j < 4; j++) acc[i][j] = 0.f;

    for (int k0 = 0; k0 < K; k0 += 32) {
        // stage W chunk (zero-padded)
        for (int t = tid; t < 32 * 128; t += 256) {
            int kk = t >> 7;
            int cc = t & 127;
            int kg = k0 + kk;
            Ws[kk][cc] = (kg < K && cc < M) ? W[kg * M + cc] : 0.f;
        }
        // stage X chunk (zero-padded)
#pragma unroll
        for (int p = 0; p < 8; p++) {
            int r = wrp + p * 8;
            int gr = row0 + r;
            int kg = k0 + lane;
            Xs[r][lane] = (gr < n && kg < K) ? X[gr * ldX + kg] : 0.f;
        }
        __syncthreads();
#pragma unroll
        for (int kk4 = 0; kk4 < 8; kk4++) {
            float4 xr[8];
#pragma unroll
            for (int i = 0; i < 8; i++)
                xr[i] = *reinterpret_cast<const float4*>(&Xs[wrp * 8 + i][kk4 * 4]);
#pragma unroll
            for (int j4 = 0; j4 < 4; j4++) {
                float4 w4 = *reinterpret_cast<const float4*>(&Ws[kk4 * 4 + j4][c]);
#pragma unroll
                for (int i = 0; i < 8; i++) {
                    float xv = (j4 == 0) ? xr[i].x : (j4 == 1) ? xr[i].y
                             : (j4 == 2) ? xr[i].z : xr[i].w;
                    acc[i][0] = fmaf(xv, w4.x, acc[i][0]);
                    acc[i][1] = fmaf(xv, w4.y, acc[i][1]);
                    acc[i][2] = fmaf(xv, w4.z, acc[i][2]);
                    acc[i][3] = fmaf(xv, w4.w, acc[i][3]);
                }
            }
        }
        __syncthreads();
    }

    // fused BatchNorm statistics (pre-activation y); padded rows/cols are exact zeros
    if (gsum) {
        if (tid < 128) { sSum[tid] = 0.f; sSq[tid] = 0.f; }
        __syncthreads();
#pragma unroll
        for (int j = 0; j < 4; j++) {
            float s = 0.f, q = 0.f;
#pragma unroll
            for (int i = 0; i < 8; i++) {
                float v = acc[i][j];
                s += v;
                q = fmaf(v, v, q);
            }
            atomicAdd(&sSum[c + j], s);
            atomicAdd(&sSq[c + j], q);
        }
        __syncthreads();
        if (tid < 128) {
            atomicAdd(&gsum[tid], sSum[tid]);
            atomicAdd(&gsq[tid], sSq[tid]);
        }
    }

#pragma unroll
    for (int i = 0; i < 8; i++) {
        int gr = row0 + wrp * 8 + i;
        if (gr >= n) break;
#pragma unroll
        for (int j = 0; j < 4; j++) {
            int cc = c + j;
            if (cc < M) {
                float v = acc[i][j];
                if (bias) v += bias[cc];
                if (doRelu) v = fmaxf(v, 0.f);
                Y[gr * ldY + cc] = v;
            } else if (cc < ldY) {
                Y[gr * ldY + cc] = 0.f;  // keep pad columns zero
            }
        }
    }
}

// ---------------- batchnorm ----------------
__global__ void bn_stats_kernel(const float* __restrict__ y, int n, int C, int ld,
                                float* gsum, float* gsq) {
    int c = threadIdx.x;  // 128 threads
    if (c >= C) return;
    int r0 = blockIdx.x * 256;
    int r1 = min(r0 + 256, n);
    float s = 0.f, q = 0.f;
    for (int r = r0; r < r1; r++) {
        float v = y[r * ld + c];
        s += v;
        q = fmaf(v, v, q);
    }
    atomicAdd(&gsum[c], s);
    atomicAdd(&gsq[c], q);
}

__global__ void bn_final_kernel(const float* gsum, const float* gsq,
                                const float* __restrict__ gamma, const float* __restrict__ beta,
                                float* scale, float* shift, int n, int C) {
    int c = threadIdx.x;
    if (c >= C) return;
    float inv_n = 1.0f / (float)n;
    float m = gsum[c] * inv_n;
    float var = gsq[c] * inv_n - m * m;
    float rs = rsqrtf(var + 1e-5f);
    float sc = gamma[c] * rs;
    scale[c] = sc;
    shift[c] = beta[c] - m * sc;
}

// apply scale/shift + relu; writes zeros to pad columns c in [C, ld)
__global__ void bn_apply_kernel(const float* __restrict__ y, float* __restrict__ xo,
                                const float* __restrict__ scale, const float* __restrict__ shift,
                                int total, int C, int ld) {
    int gid = blockIdx.x * blockDim.x + threadIdx.x;
    if (gid >= total) return;
    int c = gid % ld;
    xo[gid] = (c < C) ? fmaxf(fmaf(y[gid], scale[c], shift[c]), 0.f) : 0.f;
}

// ---------------- global sum pool (batch is sorted) ----------------
__global__ void pool_kernel(const float* __restrict__ x, const int* __restrict__ batch,
                            float* pooled, int n) {
    int c = threadIdx.x;  // 128
    int r0 = blockIdx.x * 512;
    int r1 = min(r0 + 512, n);
    float acc = 0.f;
    int cur = -1;
    for (int r = r0; r < r1; r++) {
        int g = batch[r];
        if (g != cur) {
            if (cur >= 0) atomicAdd(&pooled[cur * 128 + c], acc);
            acc = 0.f;
            cur = g;
        }
        acc += x[r * 128 + c];
    }
    if (cur >= 0) atomicAdd(&pooled[cur * 128 + c], acc);
}

// ---------------- MLP head on [16,128] ----------------
__global__ void head_kernel(const float* __restrict__ pooled,
                            const float* __restrict__ fw1, const float* __restrict__ fb1,
                            const float* __restrict__ fw2, const float* __restrict__ fb2,
                            const float* __restrict__ fw3, const float* __restrict__ fb3,
                            float* __restrict__ out) {
    __shared__ float s0[128], s1[128], s2[128];
    int t = threadIdx.x;
    int g = blockIdx.x;
    s0[t] = pooled[g * 128 + t];
    __syncthreads();
    float a = fb1[t];
    for (int k = 0; k < 128; k++) a = fmaf(s0[k], fw1[k * 128 + t], a);
    s1[t] = fmaxf(a, 0.f);
    __syncthreads();
    a = fb2[t];
    for (int k = 0; k < 128; k++) a = fmaf(s1[k], fw2[k * 128 + t], a);
    s2[t] = fmaxf(a, 0.f);
    __syncthreads();
    if (t < 100) {
        a = fb3[t];
        for (int k = 0; k < 128; k++) a = fmaf(s2[k], fw3[k * 100 + t], a);
        out[g * 100 + t] = a;
    }
}

// ---------------- launcher ----------------
extern "C" void kernel_launch(void* const* d_in, const int* in_sizes, int n_in,
                              void* d_out, int out_size) {
    const float* pos = (const float*)d_in[0];
    const int* ei = (const int*)d_in[1];     // int32
    const int* batch = (const int*)d_in[2];  // int32
    const float* w1 = (const float*)d_in[3];
    // d_in[4] = b1: cancels in BatchNorm (mean subtraction) -> skipped
    const float* g1 = (const float*)d_in[5];
    const float* be1 = (const float*)d_in[6];
    const float* w2 = (const float*)d_in[7];
    const float* g2 = (const float*)d_in[9];
    const float* be2 = (const float*)d_in[10];
    const float* w3 = (const float*)d_in[11];
    const float* g3 = (const float*)d_in[13];
    const float* be3 = (const float*)d_in[14];
    const float* fw0 = (const float*)d_in[15];
    const float* fb0 = (const float*)d_in[16];
    const float* fw1 = (const float*)d_in[17];
    const float* fb1 = (const float*)d_in[18];
    const float* fw2 = (const float*)d_in[19];
    const float* fb2 = (const float*)d_in[20];
    const float* fw3 = (const float*)d_in[21];
    const float* fb3 = (const float*)d_in[22];

    int n = in_sizes[2];       // N
    int E = in_sizes[1] / 2;   // directed edges
    const int* src = ei;
    const int* dst = ei + E;

    float *A, *B, *C, *dinv, *gsum, *gsq, *scale, *shift, *pooled;
    int *cnt, *rowptr, *cursor, *srcs, *bsum;
    cudaGetSymbolAddress((void**)&A, g_bufA);
    cudaGetSymbolAddress((void**)&B, g_bufB);
    cudaGetSymbolAddress((void**)&C, g_bufC);
    cudaGetSymbolAddress((void**)&dinv, g_dinv);
    cudaGetSymbolAddress((void**)&gsum, g_sum);
    cudaGetSymbolAddress((void**)&gsq, g_sq);
    cudaGetSymbolAddress((void**)&scale, g_scale);
    cudaGetSymbolAddress((void**)&shift, g_shift);
    cudaGetSymbolAddress((void**)&pooled, g_pool);
    cudaGetSymbolAddress((void**)&cnt, g_cnt);
    cudaGetSymbolAddress((void**)&rowptr, g_rowptr);
    cudaGetSymbolAddress((void**)&cursor, g_cursor);
    cudaGetSymbolAddress((void**)&srcs, g_srcs);
    cudaGetSymbolAddress((void**)&bsum, g_bsum);

    const int T = 256;
    int nb = ceil_div(n, 256);

    // ---- CSR build (counting sort by dst) + degrees ----
    zero_int_kernel<<<ceil_div(n, T), T>>>(cnt, n);
    hist_kernel<<<ceil_div(E, T), T>>>(cnt, dst, E);
    scan1_kernel<<<nb, 256>>>(cnt, rowptr, bsum, n);
    scan2_kernel<<<1, 32>>>(bsum, nb);
    scan3_kernel<<<nb, 256>>>(rowptr, bsum, cursor, n, E);
    reorder_kernel<<<ceil_div(E, T), T>>>(src, dst, cursor, srcs, E);
    dinv_kernel<<<ceil_div(n, T), T>>>(cnt, dinv, n);

    // ---- layer 1: pull(C=3) + GEMM 3->64 fused ----
    pull3_k3_kernel<<<ceil_div(n, T), T>>>(pos, w1, dinv, rowptr, srcs, B, n);
    zero_f_kernel<<<1, 256>>>(gsum, 128);
    zero_f_kernel<<<1, 256>>>(gsq, 128);
    bn_stats_kernel<<<ceil_div(n, 256), 128>>>(B, n, 64, 64, gsum, gsq);
    bn_final_kernel<<<1, 128>>>(gsum, gsq, g1, be1, scale, shift, n, 64);
    bn_apply_kernel<<<ceil_div(n * 64, T), T>>>(B, C, scale, shift, n * 64, 64, 64);

    // ---- layer 2: pull(64) -> GEMM 64->94 (stats fused) ----
    pull_kernel<<<ceil_div(n * 16, T), T>>>(C, A, dinv, rowptr, srcs, n, 16, 16, 4);
    zero_f_kernel<<<1, 256>>>(gsum, 128);
    zero_f_kernel<<<1, 256>>>(gsq, 128);
    gemm_kernel<<<ceil_div(n, 64), 256>>>(A, w2, nullptr, B, n, 64, 94, 64, 96, 0, gsum, gsq);
    bn_final_kernel<<<1, 128>>>(gsum, gsq, g2, be2, scale, shift, n, 94);
    bn_apply_kernel<<<ceil_div(n * 96, T), T>>>(B, C, scale, shift, n * 96, 94, 96);

    // ---- layer 3: pull(96) -> GEMM 94->128 (stats fused) ----
    pull_kernel<<<ceil_div(n * 32, T), T>>>(C, A, dinv, rowptr, srcs, n, 24, 24, 5);
    zero_f_kernel<<<1, 256>>>(gsum, 128);
    zero_f_kernel<<<1, 256>>>(gsq, 128);
    gemm_kernel<<<ceil_div(n, 64), 256>>>(A, w3, nullptr, B, n, 94, 128, 96, 128, 0, gsum, gsq);
    bn_final_kernel<<<1, 128>>>(gsum, gsq, g3, be3, scale, shift, n, 128);
    bn_apply_kernel<<<ceil_div(n * 128, T), T>>>(B, C, scale, shift, n * 128, 128, 128);

    // ---- fw0 + relu ----
    gemm_kernel<<<ceil_div(n, 64), 256>>>(C, fw0, fb0, B, n, 128, 128, 128, 128, 1,
                                          nullptr, nullptr);

    // ---- pool ----
    zero_f_kernel<<<ceil_div(16 * 128, T), T>>>(pooled, 16 * 128);
    pool_kernel<<<ceil_div(n, 512), 128>>>(B, batch, pooled, n);

    // ---- head ----
    head_kernel<<<16, 128>>>(pooled, fw1, fb1, fw2, fb2, fw3, fb3, (float*)d_out);
}

// round 7
// speedup vs baseline: 1.7728x; 1.3107x over previous
#include <cuda_runtime.h>

#define NMAX 100000
#define EMAX 600000
#define FMAX 128

// Scratch (static device globals; no runtime allocation allowed)
__device__ float g_bufA[NMAX * FMAX];
__device__ float g_bufB[NMAX * FMAX];
__device__ float g_bufC[NMAX * FMAX];
__device__ float g_dinv[NMAX];
__device__ float g_stats[2 * FMAX];   // [0:128)=sum, [128:256)=sumsq
__device__ float g_scale[FMAX];
__device__ float g_shift[FMAX];
__device__ float g_pool[16 * FMAX];
__device__ int g_cnt[NMAX];
__device__ int g_rowptr[NMAX + 1];
__device__ int g_cursor[NMAX];
__device__ int g_srcs[EMAX];
__device__ int g_bsum[1024];

static inline int ceil_div(int a, int b) { return (a + b - 1) / b; }

// ---------------- CSR build: counting sort of edges by dst ----------------
__global__ void zero_int_kernel(int* p, int n) {
    int i = blockIdx.x * blockDim.x + threadIdx.x;
    if (i < n) p[i] = 0;
}

__global__ void zero_f_kernel(float* p, int n) {
    int i = blockIdx.x * blockDim.x + threadIdx.x;
    if (i < n) p[i] = 0.f;
}

__global__ void hist_kernel(int* cnt, const int* __restrict__ dst, int E) {
    int e = blockIdx.x * blockDim.x + threadIdx.x;
    if (e < E) atomicAdd(&cnt[dst[e]], 1);
}

__global__ void scan1_kernel(const int* __restrict__ cnt, int* rowptr, int* bsum, int n) {
    __shared__ int sm[256];
    int tid = threadIdx.x;
    int gid = blockIdx.x * 256 + tid;
    int v = (gid < n) ? cnt[gid] : 0;
    sm[tid] = v;
    __syncthreads();
#pragma unroll
    for (int off = 1; off < 256; off <<= 1) {
        int t = (tid >= off) ? sm[tid - off] : 0;
        __syncthreads();
        sm[tid] += t;
        __syncthreads();
    }
    if (gid < n) rowptr[gid] = sm[tid] - v;  // exclusive
    if (tid == 255) bsum[blockIdx.x] = sm[255];
}

// parallel exclusive scan of block sums (nb <= 512)
__global__ void scan2_kernel(int* bsum, int nb) {
    __shared__ int sm[512];
    int t = threadIdx.x;
    int v = (t < nb) ? bsum[t] : 0;
    sm[t] = v;
    __syncthreads();
#pragma unroll
    for (int off = 1; off < 512; off <<= 1) {
        int x = (t >= off) ? sm[t - off] : 0;
        __syncthreads();
        sm[t] += x;
        __syncthreads();
    }
    if (t < nb) bsum[t] = sm[t] - v;  // exclusive
}

__global__ void scan3_kernel(int* rowptr, const int* __restrict__ bsum, int* cursor,
                             int n, int E) {
    int gid = blockIdx.x * blockDim.x + threadIdx.x;
    if (gid < n) {
        int r = rowptr[gid] + bsum[gid >> 8];
        rowptr[gid] = r;
        cursor[gid] = r;
    }
    if (gid == 0) rowptr[n] = E;
}

__global__ void reorder_kernel(const int* __restrict__ src, const int* __restrict__ dst,
                               int* cursor, int* srcs, int E) {
    int e = blockIdx.x * blockDim.x + threadIdx.x;
    if (e < E) {
        int p = atomicAdd(&cursor[dst[e]], 1);
        srcs[p] = src[e];
    }
}

__global__ void dinv_kernel(const int* __restrict__ cnt, float* dinv, int n) {
    int i = blockIdx.x * blockDim.x + threadIdx.x;
    if (i < n) dinv[i] = rsqrtf((float)(cnt[i] + 1));  // +1 self-loop
}

// ---------------- layer 1: pull-aggregate (C=3) fused with X@W1 (3->64) ----------------
__global__ void pull3_k3_kernel(const float* __restrict__ pos, const float* __restrict__ w1,
                                const float* __restrict__ dinv,
                                const int* __restrict__ rowptr, const int* __restrict__ srcs,
                                float* __restrict__ y, int n) {
    __shared__ float w1s[192];  // [3][64]
    int tid = threadIdx.x;
    if (tid < 192) w1s[tid] = w1[tid];
    __syncthreads();
    int v = blockIdx.x * blockDim.x + tid;
    if (v >= n) return;
    float di = dinv[v];
    float dd = di * di;
    float a0 = dd * pos[v * 3 + 0];
    float a1 = dd * pos[v * 3 + 1];
    float a2 = dd * pos[v * 3 + 2];
    int e1 = rowptr[v + 1];
    for (int e = rowptr[v]; e < e1; e++) {
        int s = srcs[e];
        float nrm = di * dinv[s];
        a0 = fmaf(nrm, pos[s * 3 + 0], a0);
        a1 = fmaf(nrm, pos[s * 3 + 1], a1);
        a2 = fmaf(nrm, pos[s * 3 + 2], a2);
    }
    float4* y4 = (float4*)(y + v * 64);
#pragma unroll
    for (int c4 = 0; c4 < 16; c4++) {
        float4 o;
        int c = c4 * 4;
        o.x = a0 * w1s[c + 0] + a1 * w1s[64 + c + 0] + a2 * w1s[128 + c + 0];
        o.y = a0 * w1s[c + 1] + a1 * w1s[64 + c + 1] + a2 * w1s[128 + c + 1];
        o.z = a0 * w1s[c + 2] + a1 * w1s[64 + c + 2] + a2 * w1s[128 + c + 2];
        o.w = a0 * w1s[c + 3] + a1 * w1s[64 + c + 3] + a2 * w1s[128 + c + 3];
        y4[c4] = o;
    }
}

// ---------------- pull-aggregate with fused BN+relu on the source ----------------
// agg = D^-1/2 (A+I) D^-1/2 relu(bn(x)).  G = 1<<gShift lanes per node.
__device__ __forceinline__ float4 bn4(float4 v, float4 sc, float4 sh) {
    float4 r;
    r.x = fmaxf(fmaf(v.x, sc.x, sh.x), 0.f);
    r.y = fmaxf(fmaf(v.y, sc.y, sh.y), 0.f);
    r.z = fmaxf(fmaf(v.z, sc.z, sh.z), 0.f);
    r.w = fmaxf(fmaf(v.w, sc.w, sh.w), 0.f);
    return r;
}

__global__ void pull_bn_kernel(const float* __restrict__ x, float* __restrict__ agg,
                               const float* __restrict__ dinv,
                               const int* __restrict__ rowptr, const int* __restrict__ srcs,
                               const float* __restrict__ scale, const float* __restrict__ shift,
                               int n, int C4, int ld4, int gShift) {
    int G = 1 << gShift;
    int group = (blockIdx.x * blockDim.x + threadIdx.x) >> gShift;
    int lane = threadIdx.x & (G - 1);
    if (group >= n || lane >= C4) return;
    float4 sc = ((const float4*)scale)[lane];
    float4 sh = ((const float4*)shift)[lane];
    float di = dinv[group];
    const float4* x4 = (const float4*)x;
    float4 xv = bn4(x4[group * ld4 + lane], sc, sh);
    float dd = di * di;
    float4 acc = make_float4(dd * xv.x, dd * xv.y, dd * xv.z, dd * xv.w);
    int e1 = rowptr[group + 1];
    for (int e = rowptr[group]; e < e1; e++) {
        int s = srcs[e];
        float nrm = di * dinv[s];
        float4 xs = bn4(x4[s * ld4 + lane], sc, sh);
        acc.x = fmaf(nrm, xs.x, acc.x);
        acc.y = fmaf(nrm, xs.y, acc.y);
        acc.z = fmaf(nrm, xs.z, acc.z);
        acc.w = fmaf(nrm, xs.w, acc.w);
    }
    ((float4*)agg)[group * ld4 + lane] = acc;
}

// ---------------- tf32 tensor-core GEMM ----------------
// Y[n,M](ldY) = X[n,K](ldX) @ W[K,M] (+bias)(+relu)(+BN-on-X at staging)(+BN stats out)
// Block: 256 threads = 8 warps as 2(M-rows) x 4(N-cols). Block tile: 128 rows x NT*32 cols.
// mma.sync.aligned.m16n8k8 tf32; fragments pre-shuffled in smem (conflict-free loads).
__device__ __forceinline__ unsigned f2tf32(float v) {
    unsigned u;
    asm("cvt.rna.tf32.f32 %0, %1;" : "=r"(u) : "f"(v));
    return u;
}

#define MMA_TF32(d, A, B)                                              \
    asm volatile(                                                      \
        "mma.sync.aligned.m16n8k8.row.col.f32.tf32.tf32.f32 "          \
        "{%0,%1,%2,%3}, {%4,%5,%6,%7}, {%8,%9}, {%0,%1,%2,%3};"        \
        : "+f"(d[0]), "+f"(d[1]), "+f"(d[2]), "+f"(d[3])               \
        : "r"(A.x), "r"(A.y), "r"(A.z), "r"(A.w), "r"(B.x), "r"(B.y))

template <int NT>  // n8-tiles per warp: 3 (96 cols) or 4 (128 cols)
__global__ __launch_bounds__(256) void gemm_tf32_kernel(
    const float* __restrict__ X, const float* __restrict__ W,
    const float* __restrict__ bias, float* __restrict__ Y,
    int n, int K, int M, int ldX, int ldY, int doRelu,
    const float* __restrict__ bnScale, const float* __restrict__ bnShift,
    float* gsum, float* gsq) {
    const int COLS = NT * 32;
    __shared__ unsigned Xfrag[4 * 8 * 32 * 4];   // [ks][mt][lane][4]
    __shared__ unsigned Wfrag[4 * 16 * 32 * 2];  // [ks][ntGlobal][lane][2]
    __shared__ float sSum[128], sSq[128];

    int tid = threadIdx.x;
    int lane = tid & 31;
    int wid = tid >> 5;
    int warpM = wid >> 2;  // 0..1
    int warpN = wid & 3;   // 0..3
    int row0 = blockIdx.x * 128;
    int g = lane >> 2, tig = lane & 3;

    float acc[4][NT][4];
#pragma unroll
    for (int mt = 0; mt < 4; mt++)
#pragma unroll
        for (int nt = 0; nt < NT; nt++)
#pragma unroll
            for (int r = 0; r < 4; r++) acc[mt][nt][r] = 0.f;

    if (gsum && tid < 128) { sSum[tid] = 0.f; sSq[tid] = 0.f; }

    for (int k0 = 0; k0 < K; k0 += 32) {
        __syncthreads();
        // stage X fragments (optionally applying BN+relu to X)
        for (int t = tid; t < 128 * 32; t += 256) {
            int row = t >> 5, kk = t & 31;
            int gr = row0 + row, kg = k0 + kk;
            float v = 0.f;
            if (gr < n && kg < K) {
                v = X[gr * ldX + kg];
                if (bnScale) v = fmaxf(fmaf(v, bnScale[kg], bnShift[kg]), 0.f);
            }
            int mt = row >> 4, r16 = row & 15;
            int gg = r16 & 7, regRow = r16 >> 3;
            int tt = kk & 3, ks = kk >> 3, j = (kk >> 2) & 1;
            Xfrag[(((ks << 3) + mt) << 7) + ((gg << 2) + tt) * 4 + regRow + 2 * j] = f2tf32(v);
        }
        // stage W fragments
        for (int t = tid; t < 32 * COLS; t += 256) {
            int kk = t / COLS, cc = t - kk * COLS;
            int kg = k0 + kk;
            float v = (kg < K && cc < M) ? W[kg * M + cc] : 0.f;
            int tt = kk & 3, ks = kk >> 3, j = (kk >> 2) & 1;
            int nt = cc >> 3, gn = cc & 7;
            Wfrag[(((ks << 4) + nt) << 6) + ((gn << 2) + tt) * 2 + j] = f2tf32(v);
        }
        __syncthreads();
#pragma unroll
        for (int ks = 0; ks < 4; ks++) {
            uint4 a[4];
            uint2 b[NT];
#pragma unroll
            for (int mt = 0; mt < 4; mt++)
                a[mt] = *(const uint4*)&Xfrag[(((ks << 3) + (warpM << 2) + mt) << 7) + (lane << 2)];
#pragma unroll
            for (int nt = 0; nt < NT; nt++)
                b[nt] = *(const uint2*)&Wfrag[(((ks << 4) + warpN * NT + nt) << 6) + (lane << 1)];
#pragma unroll
            for (int mt = 0; mt < 4; mt++)
#pragma unroll
                for (int nt = 0; nt < NT; nt++) MMA_TF32(acc[mt][nt], a[mt], b[nt]);
        }
    }

    // fused BN statistics (pre-activation); padded rows/cols are exact zeros
    if (gsum) {
#pragma unroll
        for (int nt = 0; nt < NT; nt++) {
            int cb = (warpN * NT + nt) * 8 + tig * 2;
            float s0 = 0.f, q0 = 0.f, s1 = 0.f, q1 = 0.f;
#pragma unroll
            for (int mt = 0; mt < 4; mt++) {
                float v0 = acc[mt][nt][0], v2 = acc[mt][nt][2];
                float v1 = acc[mt][nt][1], v3 = acc[mt][nt][3];
                s0 += v0 + v2; q0 += v0 * v0 + v2 * v2;
                s1 += v1 + v3; q1 += v1 * v1 + v3 * v3;
            }
            atomicAdd(&sSum[cb], s0);
            atomicAdd(&sSq[cb], q0);
            atomicAdd(&sSum[cb + 1], s1);
            atomicAdd(&sSq[cb + 1], q1);
        }
        __syncthreads();
        if (tid < 128) {
            atomicAdd(&gsum[tid], sSum[tid]);
            atomicAdd(&gsq[tid], sSq[tid]);
        }
    }

    // store
#pragma unroll
    for (int mt = 0; mt < 4; mt++) {
        int rbase = row0 + warpM * 64 + mt * 16 + g;
#pragma unroll
        for (int nt = 0; nt < NT; nt++) {
            int cb = (warpN * NT + nt) * 8 + tig * 2;
            if (cb >= ldY) continue;
            float bb0 = 0.f, bb1 = 0.f;
            if (bias) {
                if (cb < M) bb0 = bias[cb];
                if (cb + 1 < M) bb1 = bias[cb + 1];
            }
#pragma unroll
            for (int h = 0; h < 2; h++) {
                int r = rbase + h * 8;
                if (r >= n) continue;
                float v0 = acc[mt][nt][2 * h] + bb0;
                float v1 = acc[mt][nt][2 * h + 1] + bb1;
                if (doRelu) { v0 = fmaxf(v0, 0.f); v1 = fmaxf(v1, 0.f); }
                if (cb >= M) v0 = 0.f;      // pad column -> keep zero
                if (cb + 1 >= M) v1 = 0.f;
                *(float2*)&Y[r * ldY + cb] = make_float2(v0, v1);
            }
        }
    }
}

// ---------------- batchnorm ----------------
__global__ void bn_stats_kernel(const float* __restrict__ y, int n, int C, int ld,
                                float* gsum, float* gsq) {
    int c = threadIdx.x;  // 128 threads
    if (c >= C) return;
    int r0 = blockIdx.x * 256;
    int r1 = min(r0 + 256, n);
    float s = 0.f, q = 0.f;
    for (int r = r0; r < r1; r++) {
        float v = y[r * ld + c];
        s += v;
        q = fmaf(v, v, q);
    }
    atomicAdd(&gsum[c], s);
    atomicAdd(&gsq[c], q);
}

__global__ void bn_final_kernel(const float* gsum, const float* gsq,
                                const float* __restrict__ gamma, const float* __restrict__ beta,
                                float* scale, float* shift, int n, int C) {
    int c = threadIdx.x;
    if (c >= C) return;
    float inv_n = 1.0f / (float)n;
    float m = gsum[c] * inv_n;
    float var = gsq[c] * inv_n - m * m;
    float rs = rsqrtf(var + 1e-5f);
    float sc = gamma[c] * rs;
    scale[c] = sc;
    shift[c] = beta[c] - m * sc;
}

// ---------------- global sum pool (batch is sorted) ----------------
__global__ void pool_kernel(const float* __restrict__ x, const int* __restrict__ batch,
                            float* pooled, int n) {
    int c = threadIdx.x;  // 128
    int r0 = blockIdx.x * 512;
    int r1 = min(r0 + 512, n);
    float acc = 0.f;
    int cur = -1;
    for (int r = r0; r < r1; r++) {
        int g = batch[r];
        if (g != cur) {
            if (cur >= 0) atomicAdd(&pooled[cur * 128 + c], acc);
            acc = 0.f;
            cur = g;
        }
        acc += x[r * 128 + c];
    }
    if (cur >= 0) atomicAdd(&pooled[cur * 128 + c], acc);
}

// ---------------- MLP head on [16,128] ----------------
__global__ void head_kernel(const float* __restrict__ pooled,
                            const float* __restrict__ fw1, const float* __restrict__ fb1,
                            const float* __restrict__ fw2, const float* __restrict__ fb2,
                            const float* __restrict__ fw3, const float* __restrict__ fb3,
                            float* __restrict__ out) {
    __shared__ float s0[128], s1[128], s2[128];
    int t = threadIdx.x;
    int g = blockIdx.x;
    s0[t] = pooled[g * 128 + t];
    __syncthreads();
    float a = fb1[t];
    for (int k = 0; k < 128; k++) a = fmaf(s0[k], fw1[k * 128 + t], a);
    s1[t] = fmaxf(a, 0.f);
    __syncthreads();
    a = fb2[t];
    for (int k = 0; k < 128; k++) a = fmaf(s1[k], fw2[k * 128 + t], a);
    s2[t] = fmaxf(a, 0.f);
    __syncthreads();
    if (t < 100) {
        a = fb3[t];
        for (int k = 0; k < 128; k++) a = fmaf(s2[k], fw3[k * 100 + t], a);
        out[g * 100 + t] = a;
    }
}

// ---------------- launcher ----------------
extern "C" void kernel_launch(void* const* d_in, const int* in_sizes, int n_in,
                              void* d_out, int out_size) {
    const float* pos = (const float*)d_in[0];
    const int* ei = (const int*)d_in[1];     // int32
    const int* batch = (const int*)d_in[2];  // int32
    const float* w1 = (const float*)d_in[3];
    // d_in[4] = b1: cancels in BatchNorm (mean subtraction) -> skipped
    const float* g1 = (const float*)d_in[5];
    const float* be1 = (const float*)d_in[6];
    const float* w2 = (const float*)d_in[7];
    const float* g2 = (const float*)d_in[9];
    const float* be2 = (const float*)d_in[10];
    const float* w3 = (const float*)d_in[11];
    const float* g3 = (const float*)d_in[13];
    const float* be3 = (const float*)d_in[14];
    const float* fw0 = (const float*)d_in[15];
    const float* fb0 = (const float*)d_in[16];
    const float* fw1 = (const float*)d_in[17];
    const float* fb1 = (const float*)d_in[18];
    const float* fw2 = (const float*)d_in[19];
    const float* fb2 = (const float*)d_in[20];
    const float* fw3 = (const float*)d_in[21];
    const float* fb3 = (const float*)d_in[22];

    int n = in_sizes[2];       // N
    int E = in_sizes[1] / 2;   // directed edges
    const int* src = ei;
    const int* dst = ei + E;

    float *A, *B, *C, *dinv, *stats, *scale, *shift, *pooled;
    int *cnt, *rowptr, *cursor, *srcs, *bsum;
    cudaGetSymbolAddress((void**)&A, g_bufA);
    cudaGetSymbolAddress((void**)&B, g_bufB);
    cudaGetSymbolAddress((void**)&C, g_bufC);
    cudaGetSymbolAddress((void**)&dinv, g_dinv);
    cudaGetSymbolAddress((void**)&stats, g_stats);
    cudaGetSymbolAddress((void**)&scale, g_scale);
    cudaGetSymbolAddress((void**)&shift, g_shift);
    cudaGetSymbolAddress((void**)&pooled, g_pool);
    cudaGetSymbolAddress((void**)&cnt, g_cnt);
    cudaGetSymbolAddress((void**)&rowptr, g_rowptr);
    cudaGetSymbolAddress((void**)&cursor, g_cursor);
    cudaGetSymbolAddress((void**)&srcs, g_srcs);
    cudaGetSymbolAddress((void**)&bsum, g_bsum);
    float* gsum = stats;
    float* gsq = stats + 128;

    const int T = 256;
    int nb = ceil_div(n, 256);
    int gemmBlocks = ceil_div(n, 128);

    // ---- CSR build (counting sort by dst) + degrees ----
    zero_int_kernel<<<ceil_div(n, T), T>>>(cnt, n);
    hist_kernel<<<ceil_div(E, T), T>>>(cnt, dst, E);
    scan1_kernel<<<nb, 256>>>(cnt, rowptr, bsum, n);
    scan2_kernel<<<1, 512>>>(bsum, nb);
    scan3_kernel<<<nb, 256>>>(rowptr, bsum, cursor, n, E);
    reorder_kernel<<<ceil_div(E, T), T>>>(src, dst, cursor, srcs, E);
    dinv_kernel<<<ceil_div(n, T), T>>>(cnt, dinv, n);

    // ---- layer 1: pull(C=3) + GEMM 3->64 fused -> B (pre-BN) ----
    pull3_k3_kernel<<<ceil_div(n, T), T>>>(pos, w1, dinv, rowptr, srcs, B, n);
    zero_f_kernel<<<1, 256>>>(stats, 256);
    bn_stats_kernel<<<ceil_div(n, 256), 128>>>(B, n, 64, 64, gsum, gsq);
    bn_final_kernel<<<1, 128>>>(gsum, gsq, g1, be1, scale, shift, n, 64);

    // ---- layer 2: pull(BN1 fused) -> A [n,64]; tf32 GEMM 64->94 -> B [n,96] + stats ----
    pull_bn_kernel<<<ceil_div(n * 16, T), T>>>(B, A, dinv, rowptr, srcs, scale, shift,
                                               n, 16, 16, 4);
    zero_f_kernel<<<1, 256>>>(stats, 256);
    gemm_tf32_kernel<3><<<gemmBlocks, 256>>>(A, w2, nullptr, B, n, 64, 94, 64, 96, 0,
                                             nullptr, nullptr, gsum, gsq);
    bn_final_kernel<<<1, 128>>>(gsum, gsq, g2, be2, scale, shift, n, 94);

    // ---- layer 3: pull(BN2 fused) -> A [n,96]; tf32 GEMM 94->128 -> B [n,128] + stats ----
    pull_bn_kernel<<<ceil_div(n * 32, T), T>>>(B, A, dinv, rowptr, srcs, scale, shift,
                                               n, 24, 24, 5);
    zero_f_kernel<<<1, 256>>>(stats, 256);
    gemm_tf32_kernel<4><<<gemmBlocks, 256>>>(A, w3, nullptr, B, n, 94, 128, 96, 128, 0,
                                             nullptr, nullptr, gsum, gsq);
    bn_final_kernel<<<1, 128>>>(gsum, gsq, g3, be3, scale, shift, n, 128);

    // ---- fw0: BN3+relu fused into X staging; +bias +relu -> C [n,128] ----
    gemm_tf32_kernel<4><<<gemmBlocks, 256>>>(B, fw0, fb0, C, n, 128, 128, 128, 128, 1,
                                             scale, shift, nullptr, nullptr);

    // ---- pool ----
    zero_f_kernel<<<ceil_div(16 * 128, T), T>>>(pooled, 16 * 128);
    pool_kernel<<<ceil_div(n, 512), 128>>>(C, batch, pooled, n);

    // ---- head ----
    head_kernel<<<16, 128>>>(pooled, fw1, fb1, fw2, fb2, fw3, fb3, (float*)d_out);
}